// round 4
// baseline (speedup 1.0000x reference)
#include <cuda_runtime.h>
#include <cstdint>

#define TSEQ 2048
#define NB   4
#define DM   1024
#define M_TOT (NB * TSEQ)   // 8192

// Scratch (device globals: allocation-free per harness rules)
__device__ float g_qkv[(size_t)NB * TSEQ * 3 * DM]; // [B,T,3C]
__device__ float g_att[(size_t)NB * TSEQ * DM];     // [B,T,C]

__device__ __forceinline__ float cvt_tf32(float x) {
    uint32_t u;
    asm("cvt.rna.tf32.f32 %0, %1;" : "=r"(u) : "f"(x));
    return __uint_as_float(u);
}

__device__ __forceinline__ void mma_tf32(
    float& c0, float& c1, float& c2, float& c3,
    uint32_t a0, uint32_t a1, uint32_t a2, uint32_t a3,
    uint32_t b0, uint32_t b1)
{
    asm volatile(
        "mma.sync.aligned.m16n8k8.row.col.f32.tf32.tf32.f32 "
        "{%0,%1,%2,%3}, {%4,%5,%6,%7}, {%8,%9}, {%0,%1,%2,%3};"
        : "+f"(c0), "+f"(c1), "+f"(c2), "+f"(c3)
        : "r"(a0), "r"(a1), "r"(a2), "r"(a3), "r"(b0), "r"(b1));
}

// ---------------------------------------------------------------------------
// TF32 tensor-core GEMM: C[M,N] = A[M,K] @ B[K,N] (+bias)
// 128x128 CTA tile, BK=32, 256 threads, 8 warps (2x4) of 64x32.
// Double-buffered smem (1 barrier per slab). A stored k-permuted
// (pos = (k&3)*8 + (k>>2), row stride 34) -> LDS.64 fragment loads,
// conflict-free. rna tf32 conversion at STS time.
// ---------------------------------------------------------------------------
#define ASTR 34
#define ABUF (128 * ASTR)
#define BSTR 132
#define BBUF (32 * BSTR)

template <int BIAS>
__global__ void __launch_bounds__(256) gemm_tf32(
    const float* __restrict__ A, const float* __restrict__ Bm,
    const float* __restrict__ bias, float* __restrict__ C,
    int M, int N, int K)
{
    extern __shared__ float smem[];
    float* Asm = smem;                 // [2][128*ASTR]
    float* Bsm = smem + 2 * ABUF;      // [2][32*BSTR]

    const int tid  = threadIdx.x;
    const int lane = tid & 31;
    const int wid  = tid >> 5;
    const int wm   = (wid & 1) * 64;
    const int wn   = (wid >> 1) * 32;
    const int bm   = blockIdx.y * 128;
    const int bn   = blockIdx.x * 128;
    const int qr   = lane >> 2;
    const int qc   = lane & 3;

    const int arow = tid >> 3;         // +32*t
    const int j0   = tid & 7;          // A k-cols 4*j0..4*j0+3
    const int brow = tid >> 5;         // +8*t
    const int bcol = (tid & 31) << 2;

    const float* Ag = A  + (size_t)bm * K;
    const float* Bg = Bm + bn;

    float acc[4][4][4];
#pragma unroll
    for (int mi = 0; mi < 4; mi++)
#pragma unroll
        for (int ni = 0; ni < 4; ni++)
#pragma unroll
            for (int c = 0; c < 4; c++) acc[mi][ni][c] = 0.f;

    float4 pa[4], pb[4];

    auto ldg = [&](int k0) {
#pragma unroll
        for (int t = 0; t < 4; t++) {
            pa[t] = *(const float4*)(Ag + (size_t)(arow + 32 * t) * K + k0 + 4 * j0);
            pb[t] = *(const float4*)(Bg + (size_t)(k0 + brow + 8 * t) * N + bcol);
        }
    };
    auto sts = [&](int buf) {
        float* Ab = Asm + buf * ABUF;
        float* Bb = Bsm + buf * BBUF;
#pragma unroll
        for (int t = 0; t < 4; t++) {
            float* ap = Ab + (arow + 32 * t) * ASTR + j0;
            ap[0]  = cvt_tf32(pa[t].x);
            ap[8]  = cvt_tf32(pa[t].y);
            ap[16] = cvt_tf32(pa[t].z);
            ap[24] = cvt_tf32(pa[t].w);
            float4 bw;
            bw.x = cvt_tf32(pb[t].x); bw.y = cvt_tf32(pb[t].y);
            bw.z = cvt_tf32(pb[t].z); bw.w = cvt_tf32(pb[t].w);
            *(float4*)(Bb + (brow + 8 * t) * BSTR + bcol) = bw;
        }
    };
    auto compute = [&](int buf) {
        const float* Ab = Asm + buf * ABUF;
        const float* Bb = Bsm + buf * BBUF;
#pragma unroll
        for (int kk = 0; kk < 4; kk++) {
            uint32_t af[4][4], bf[4][2];
#pragma unroll
            for (int mi = 0; mi < 4; mi++) {
                const float* ap = Ab + (wm + mi * 16 + qr) * ASTR + qc * 8 + 2 * kk;
                float2 lo = *(const float2*)ap;
                float2 hi = *(const float2*)(ap + 8 * ASTR);
                af[mi][0] = __float_as_uint(lo.x);
                af[mi][2] = __float_as_uint(lo.y);
                af[mi][1] = __float_as_uint(hi.x);
                af[mi][3] = __float_as_uint(hi.y);
            }
#pragma unroll
            for (int ni = 0; ni < 4; ni++) {
                const int n = wn + ni * 8 + qr;
                bf[ni][0] = __float_as_uint(Bb[(kk * 8 + qc) * BSTR + n]);
                bf[ni][1] = __float_as_uint(Bb[(kk * 8 + qc + 4) * BSTR + n]);
            }
#pragma unroll
            for (int mi = 0; mi < 4; mi++)
#pragma unroll
                for (int ni = 0; ni < 4; ni++)
                    mma_tf32(acc[mi][ni][0], acc[mi][ni][1],
                             acc[mi][ni][2], acc[mi][ni][3],
                             af[mi][0], af[mi][1], af[mi][2], af[mi][3],
                             bf[ni][0], bf[ni][1]);
        }
    };

    const int nslab = K >> 5;
    ldg(0);
    sts(0);
    ldg(32);
    __syncthreads();

    for (int s = 0; s < nslab; s++) {
        const int cur = s & 1;
        compute(cur);
        if (s + 1 < nslab) {
            sts(1 - cur);
            if (s + 2 < nslab) ldg((s + 2) << 5);
            __syncthreads();
        }
    }

    // epilogue
#pragma unroll
    for (int mi = 0; mi < 4; mi++) {
        const int r0 = bm + wm + mi * 16 + qr;
#pragma unroll
        for (int ni = 0; ni < 4; ni++) {
            const int cc = bn + wn + ni * 8 + qc * 2;
            float b0 = 0.f, b1 = 0.f;
            if (BIAS) { b0 = bias[cc]; b1 = bias[cc + 1]; }
            float2 t0, t1;
            t0.x = acc[mi][ni][0] + b0; t0.y = acc[mi][ni][1] + b1;
            t1.x = acc[mi][ni][2] + b0; t1.y = acc[mi][ni][3] + b1;
            *(float2*)(C + (size_t)r0 * N + cc)       = t0;
            *(float2*)(C + (size_t)(r0 + 8) * N + cc) = t1;
        }
    }
}

// ---------------------------------------------------------------------------
// Flash attention (causal), TF32 tensor cores, double-buffered K/V tiles.
// CTA = (b, h, 128-row q-tile), 8 warps x 16 rows, BC=64.
// One barrier per KV tile. Heavy tiles launch first (reversed q0).
// ---------------------------------------------------------------------------
#define QSTR 68
#define KVBUF (64 * QSTR)

__global__ void __launch_bounds__(256) attn_mma(
    const float* __restrict__ qkv, float* __restrict__ out)
{
    extern __shared__ float sm[];
    float* Qs = sm;                       // [128][QSTR]
    float* Ks = Qs + 128 * QSTR;          // [2][64][QSTR]
    float* Vs = Ks + 2 * KVBUF;           // [2][64][QSTR]
    float* Ps = Vs + 2 * KVBUF;           // [128][QSTR]

    const int tid  = threadIdx.x;
    const int lane = tid & 31;
    const int wid  = tid >> 5;
    const int wm   = wid * 16;
    const int qr   = lane >> 2;
    const int qc   = lane & 3;
    const int q0   = (int)(gridDim.x - 1 - blockIdx.x) * 128;  // heavy first
    const int b    = blockIdx.y >> 4;
    const int h    = blockIdx.y & 15;

    const float* base = qkv + (size_t)b * TSEQ * (3 * DM) + h * 64;

    // Load Q tile (pre-scaled, tf32)
    for (int i = tid; i < 128 * 16; i += 256) {
        int row = i >> 4, d0 = (i & 15) << 2;
        float4 v = *(const float4*)(base + (size_t)(q0 + row) * (3 * DM) + d0);
        float4 w;
        w.x = cvt_tf32(v.x * 0.125f); w.y = cvt_tf32(v.y * 0.125f);
        w.z = cvt_tf32(v.z * 0.125f); w.w = cvt_tf32(v.w * 0.125f);
        *(float4*)&Qs[row * QSTR + d0] = w;
    }

    float4 pk[4], pv[4];
    auto ldgKV = [&](int k0) {
#pragma unroll
        for (int t = 0; t < 4; t++) {
            int i = tid + 256 * t;
            int key = i >> 4, d0 = (i & 15) << 2;
            const float* kp = base + DM + (size_t)(k0 + key) * (3 * DM) + d0;
            pk[t] = *(const float4*)kp;
            pv[t] = *(const float4*)(kp + DM);
        }
    };
    auto stsKV = [&](int buf) {
        float* Kb = Ks + buf * KVBUF;
        float* Vb = Vs + buf * KVBUF;
#pragma unroll
        for (int t = 0; t < 4; t++) {
            int i = tid + 256 * t;
            int key = i >> 4, d0 = (i & 15) << 2;
            float4 kw, vw;
            kw.x = cvt_tf32(pk[t].x); kw.y = cvt_tf32(pk[t].y);
            kw.z = cvt_tf32(pk[t].z); kw.w = cvt_tf32(pk[t].w);
            vw.x = cvt_tf32(pv[t].x); vw.y = cvt_tf32(pv[t].y);
            vw.z = cvt_tf32(pv[t].z); vw.w = cvt_tf32(pv[t].w);
            *(float4*)&Kb[key * QSTR + d0] = kw;
            *(float4*)&Vb[key * QSTR + d0] = vw;
        }
    };

    float oacc[8][4];
#pragma unroll
    for (int ni = 0; ni < 8; ni++)
#pragma unroll
        for (int c = 0; c < 4; c++) oacc[ni][c] = 0.f;
    float m0 = -1e30f, m1 = -1e30f, l0 = 0.f, l1 = 0.f;

    const int r0g = q0 + wm + qr;
    const int r1g = r0g + 8;
    const int ntiles = (q0 >> 6) + 2;

    ldgKV(0);
    stsKV(0);
    ldgKV(64);
    __syncthreads();

    for (int j = 0; j < ntiles; j++) {
        const int cur = j & 1;
        const int k0 = j << 6;
        const float* Kb = Ks + cur * KVBUF;
        const float* Vb = Vs + cur * KVBUF;

        // ---- S = Q @ K^T ----
        float sacc[8][4];
#pragma unroll
        for (int ni = 0; ni < 8; ni++)
#pragma unroll
            for (int c = 0; c < 4; c++) sacc[ni][c] = 0.f;

#pragma unroll
        for (int kb = 0; kb < 64; kb += 8) {
            uint32_t a0 = __float_as_uint(Qs[(wm + qr) * QSTR + kb + qc]);
            uint32_t a1 = __float_as_uint(Qs[(wm + qr + 8) * QSTR + kb + qc]);
            uint32_t a2 = __float_as_uint(Qs[(wm + qr) * QSTR + kb + qc + 4]);
            uint32_t a3 = __float_as_uint(Qs[(wm + qr + 8) * QSTR + kb + qc + 4]);
#pragma unroll
            for (int ni = 0; ni < 8; ni++) {
                uint32_t b0 = __float_as_uint(Kb[(ni * 8 + qr) * QSTR + kb + qc]);
                uint32_t b1 = __float_as_uint(Kb[(ni * 8 + qr) * QSTR + kb + qc + 4]);
                mma_tf32(sacc[ni][0], sacc[ni][1], sacc[ni][2], sacc[ni][3],
                         a0, a1, a2, a3, b0, b1);
            }
        }

        // ---- online softmax ----
        const bool domask = (k0 + 63 > q0 + wm);
        float mx0 = -1e30f, mx1 = -1e30f;
#pragma unroll
        for (int ni = 0; ni < 8; ni++) {
            if (domask) {
                const int cb = k0 + ni * 8 + qc * 2;
                if (cb     > r0g) sacc[ni][0] = -1e30f;
                if (cb + 1 > r0g) sacc[ni][1] = -1e30f;
                if (cb     > r1g) sacc[ni][2] = -1e30f;
                if (cb + 1 > r1g) sacc[ni][3] = -1e30f;
            }
            mx0 = fmaxf(mx0, fmaxf(sacc[ni][0], sacc[ni][1]));
            mx1 = fmaxf(mx1, fmaxf(sacc[ni][2], sacc[ni][3]));
        }
        mx0 = fmaxf(mx0, __shfl_xor_sync(0xffffffffu, mx0, 1));
        mx0 = fmaxf(mx0, __shfl_xor_sync(0xffffffffu, mx0, 2));
        mx1 = fmaxf(mx1, __shfl_xor_sync(0xffffffffu, mx1, 1));
        mx1 = fmaxf(mx1, __shfl_xor_sync(0xffffffffu, mx1, 2));

        const float mn0 = fmaxf(m0, mx0), mn1 = fmaxf(m1, mx1);
        const float sc0 = __expf(m0 - mn0), sc1 = __expf(m1 - mn1);
        float rs0 = 0.f, rs1 = 0.f;
#pragma unroll
        for (int ni = 0; ni < 8; ni++) {
            float p0 = __expf(sacc[ni][0] - mn0);
            float p1 = __expf(sacc[ni][1] - mn0);
            float p2 = __expf(sacc[ni][2] - mn1);
            float p3 = __expf(sacc[ni][3] - mn1);
            rs0 += p0 + p1; rs1 += p2 + p3;
            float2 t0; t0.x = cvt_tf32(p0); t0.y = cvt_tf32(p1);
            float2 t1; t1.x = cvt_tf32(p2); t1.y = cvt_tf32(p3);
            *(float2*)&Ps[(wm + qr) * QSTR + ni * 8 + qc * 2]     = t0;
            *(float2*)&Ps[(wm + qr + 8) * QSTR + ni * 8 + qc * 2] = t1;
            oacc[ni][0] *= sc0; oacc[ni][1] *= sc0;
            oacc[ni][2] *= sc1; oacc[ni][3] *= sc1;
        }
        rs0 += __shfl_xor_sync(0xffffffffu, rs0, 1);
        rs0 += __shfl_xor_sync(0xffffffffu, rs0, 2);
        rs1 += __shfl_xor_sync(0xffffffffu, rs1, 1);
        rs1 += __shfl_xor_sync(0xffffffffu, rs1, 2);
        l0 = l0 * sc0 + rs0; l1 = l1 * sc1 + rs1;
        m0 = mn0; m1 = mn1;
        __syncwarp();

        // ---- O += P @ V ----
#pragma unroll
        for (int kb = 0; kb < 64; kb += 8) {
            uint32_t a0 = __float_as_uint(Ps[(wm + qr) * QSTR + kb + qc]);
            uint32_t a1 = __float_as_uint(Ps[(wm + qr + 8) * QSTR + kb + qc]);
            uint32_t a2 = __float_as_uint(Ps[(wm + qr) * QSTR + kb + qc + 4]);
            uint32_t a3 = __float_as_uint(Ps[(wm + qr + 8) * QSTR + kb + qc + 4]);
#pragma unroll
            for (int ni = 0; ni < 8; ni++) {
                uint32_t b0 = __float_as_uint(Vb[(kb + qc) * QSTR + ni * 8 + qr]);
                uint32_t b1 = __float_as_uint(Vb[(kb + qc + 4) * QSTR + ni * 8 + qr]);
                mma_tf32(oacc[ni][0], oacc[ni][1], oacc[ni][2], oacc[ni][3],
                         a0, a1, a2, a3, b0, b1);
            }
        }

        if (j + 1 < ntiles) {
            stsKV(1 - cur);
            if (j + 2 < ntiles) ldgKV((j + 2) << 6);
            __syncthreads();
        }
    }

    // Normalize + write out[b, t, h*64 + d]
    const float inv0 = 1.f / l0, inv1 = 1.f / l1;
    float* o0 = out + ((size_t)b * TSEQ + r0g) * DM + h * 64;
    float* o1 = out + ((size_t)b * TSEQ + r1g) * DM + h * 64;
#pragma unroll
    for (int ni = 0; ni < 8; ni++) {
        const int cc = ni * 8 + qc * 2;
        float2 t0; t0.x = oacc[ni][0] * inv0; t0.y = oacc[ni][1] * inv0;
        float2 t1; t1.x = oacc[ni][2] * inv1; t1.y = oacc[ni][3] * inv1;
        *(float2*)(o0 + cc) = t0;
        *(float2*)(o1 + cc) = t1;
    }
}

// ---------------------------------------------------------------------------
extern "C" void kernel_launch(void* const* d_in, const int* in_sizes, int n_in,
                              void* d_out, int out_size)
{
    const float* x      = (const float*)d_in[0];
    const float* w_qkv  = (const float*)d_in[1];
    const float* w_proj = (const float*)d_in[2];
    const float* b_proj = (const float*)d_in[3];
    float* out = (float*)d_out;

    float* qkv; cudaGetSymbolAddress((void**)&qkv, g_qkv);
    float* att; cudaGetSymbolAddress((void**)&att, g_att);

    const int GSMEM = (2 * ABUF + 2 * BBUF) * 4;   // 68608 B
    cudaFuncSetAttribute(gemm_tf32<0>,
                         cudaFuncAttributeMaxDynamicSharedMemorySize, GSMEM);
    cudaFuncSetAttribute(gemm_tf32<1>,
                         cudaFuncAttributeMaxDynamicSharedMemorySize, GSMEM);
    const int ASMEM = (128 * QSTR + 4 * KVBUF + 128 * QSTR) * 4;  // 139264 B
    cudaFuncSetAttribute(attn_mma,
                         cudaFuncAttributeMaxDynamicSharedMemorySize, ASMEM);

    // 1) QKV = x @ w_qkv   (8192 x 3072 x 1024)
    gemm_tf32<0><<<dim3(3 * DM / 128, M_TOT / 128), 256, GSMEM>>>(
        x, w_qkv, nullptr, qkv, M_TOT, 3 * DM, DM);

    // 2) causal MHA -> att [B,T,C]
    attn_mma<<<dim3(TSEQ / 128, NB * 16), 256, ASMEM>>>(qkv, att);

    // 3) out = att @ w_proj + b_proj   (8192 x 1024 x 1024)
    gemm_tf32<1><<<dim3(DM / 128, M_TOT / 128), 256, GSMEM>>>(
        att, w_proj, b_proj, out, M_TOT, DM, DM);
}

// round 5
// speedup vs baseline: 1.2428x; 1.2428x over previous
#include <cuda_runtime.h>
#include <cstdint>

#define TSEQ 2048
#define NB   4
#define DM   1024
#define M_TOT (NB * TSEQ)   // 8192

// Scratch (device globals: allocation-free per harness rules)
__device__ float g_qkv[(size_t)NB * TSEQ * 3 * DM]; // [B,T,3C] tf32-rounded (Q pre-scaled)
__device__ float g_att[(size_t)NB * TSEQ * DM];     // [B,T,C]  tf32-rounded
__device__ float g_xr[(size_t)M_TOT * DM];          // rna(x)
__device__ float g_wq[(size_t)DM * 3 * DM];         // rna(w_qkv)
__device__ float g_wp[(size_t)DM * DM];             // rna(w_proj)

__device__ __forceinline__ float cvt_tf32(float x) {
    uint32_t u;
    asm("cvt.rna.tf32.f32 %0, %1;" : "=r"(u) : "f"(x));
    return __uint_as_float(u);
}

__device__ __forceinline__ void mma_tf32(
    float& c0, float& c1, float& c2, float& c3,
    uint32_t a0, uint32_t a1, uint32_t a2, uint32_t a3,
    uint32_t b0, uint32_t b1)
{
    asm volatile(
        "mma.sync.aligned.m16n8k8.row.col.f32.tf32.tf32.f32 "
        "{%0,%1,%2,%3}, {%4,%5,%6,%7}, {%8,%9}, {%0,%1,%2,%3};"
        : "+f"(c0), "+f"(c1), "+f"(c2), "+f"(c3)
        : "r"(a0), "r"(a1), "r"(a2), "r"(a3), "r"(b0), "r"(b1));
}

__device__ __forceinline__ uint32_t smem_u32(const void* p) {
    return (uint32_t)__cvta_generic_to_shared(p);
}
#define CP_ASYNC16(dst, src) \
    asm volatile("cp.async.cg.shared.global [%0], [%1], 16;" :: "r"(dst), "l"(src))
#define CP_COMMIT() asm volatile("cp.async.commit_group;")
#define CP_WAIT(n)  asm volatile("cp.async.wait_group %0;" :: "n"(n))

// ---------------------------------------------------------------------------
// Elementwise rna-tf32 rounding (pre-pass)
// ---------------------------------------------------------------------------
__global__ void round_tf32(const float4* __restrict__ in,
                           float4* __restrict__ out, int n4)
{
    int i = blockIdx.x * blockDim.x + threadIdx.x;
    int stride = gridDim.x * blockDim.x;
    for (; i < n4; i += stride) {
        float4 v = in[i];
        float4 w;
        w.x = cvt_tf32(v.x); w.y = cvt_tf32(v.y);
        w.z = cvt_tf32(v.z); w.w = cvt_tf32(v.w);
        out[i] = w;
    }
}

// ---------------------------------------------------------------------------
// TF32 tensor-core GEMM with cp.async 2-stage pipeline, 2 CTAs/SM.
// Inputs must already be tf32-rounded. 128x128 CTA tile, BK=32, 256 threads.
// EPI=0: C = acc + bias (fp32, final output)
// EPI=1: C = cvt_tf32(acc * (col<1024 ? 0.125 : 1))  (qkv scratch)
// ---------------------------------------------------------------------------
#define ASTR 36
#define ASTG (128 * ASTR)
#define BSTR 132
#define BSTG (32 * BSTR)

template <int EPI>
__global__ void __launch_bounds__(256, 2) gemm_async(
    const float* __restrict__ A, const float* __restrict__ Bm,
    const float* __restrict__ bias, float* __restrict__ C,
    int M, int N, int K)
{
    extern __shared__ float smem[];
    float* Asm = smem;                 // [2][ASTG]
    float* Bsm = smem + 2 * ASTG;      // [2][BSTG]
    const uint32_t As_u = smem_u32(Asm);
    const uint32_t Bs_u = smem_u32(Bsm);

    const int tid  = threadIdx.x;
    const int lane = tid & 31;
    const int wid  = tid >> 5;
    const int wm   = (wid & 1) * 64;
    const int wn   = (wid >> 1) * 32;
    const int bm   = blockIdx.y * 128;
    const int bn   = blockIdx.x * 128;
    const int qr   = lane >> 2;
    const int qc   = lane & 3;

    const int arow = tid >> 3;          // +32*t
    const int acol = (tid & 7) << 2;
    const int brow = tid >> 5;          // +8*t
    const int bcol = (tid & 31) << 2;

    const float* Ag = A  + (size_t)bm * K;
    const float* Bg = Bm + bn;

    float acc[4][4][4];
#pragma unroll
    for (int mi = 0; mi < 4; mi++)
#pragma unroll
        for (int ni = 0; ni < 4; ni++)
#pragma unroll
            for (int c = 0; c < 4; c++) acc[mi][ni][c] = 0.f;

    auto ldgsts = [&](int stage, int k0) {
#pragma unroll
        for (int t = 0; t < 4; t++) {
            CP_ASYNC16(As_u + ((stage * ASTG + (arow + 32 * t) * ASTR + acol) << 2),
                       Ag + (size_t)(arow + 32 * t) * K + k0 + acol);
            CP_ASYNC16(Bs_u + ((stage * BSTG + (brow + 8 * t) * BSTR + bcol) << 2),
                       Bg + (size_t)(k0 + brow + 8 * t) * N + bcol);
        }
        CP_COMMIT();
    };

    auto compute = [&](int stage) {
        const float* Ab = Asm + stage * ASTG;
        const float* Bb = Bsm + stage * BSTG;
#pragma unroll
        for (int kk = 0; kk < 4; kk++) {
            const int kb = kk * 8;
            uint32_t af[4][4], bf[4][2];
#pragma unroll
            for (int mi = 0; mi < 4; mi++) {
                const float* ap = Ab + (wm + mi * 16 + qr) * ASTR + kb + qc;
                af[mi][0] = __float_as_uint(ap[0]);
                af[mi][1] = __float_as_uint(ap[8 * ASTR]);
                af[mi][2] = __float_as_uint(ap[4]);
                af[mi][3] = __float_as_uint(ap[8 * ASTR + 4]);
            }
#pragma unroll
            for (int ni = 0; ni < 4; ni++) {
                const int n = wn + ni * 8 + qr;
                bf[ni][0] = __float_as_uint(Bb[(kb + qc) * BSTR + n]);
                bf[ni][1] = __float_as_uint(Bb[(kb + qc + 4) * BSTR + n]);
            }
#pragma unroll
            for (int mi = 0; mi < 4; mi++)
#pragma unroll
                for (int ni = 0; ni < 4; ni++)
                    mma_tf32(acc[mi][ni][0], acc[mi][ni][1],
                             acc[mi][ni][2], acc[mi][ni][3],
                             af[mi][0], af[mi][1], af[mi][2], af[mi][3],
                             bf[ni][0], bf[ni][1]);
        }
    };

    const int nslab = K >> 5;
    ldgsts(0, 0);
    ldgsts(1, 32);

    for (int s = 0; s < nslab; s++) {
        CP_WAIT(1);
        __syncthreads();
        compute(s & 1);
        __syncthreads();
        if (s + 2 < nslab) ldgsts(s & 1, (s + 2) << 5);
        else               CP_COMMIT();   // keep group count in step
    }

    // epilogue
#pragma unroll
    for (int mi = 0; mi < 4; mi++) {
        const int r0 = bm + wm + mi * 16 + qr;
#pragma unroll
        for (int ni = 0; ni < 4; ni++) {
            const int cc = bn + wn + ni * 8 + qc * 2;
            float2 t0, t1;
            if (EPI == 1) {
                const float cs = (cc < DM) ? 0.125f : 1.0f;
                t0.x = cvt_tf32(acc[mi][ni][0] * cs);
                t0.y = cvt_tf32(acc[mi][ni][1] * cs);
                t1.x = cvt_tf32(acc[mi][ni][2] * cs);
                t1.y = cvt_tf32(acc[mi][ni][3] * cs);
            } else {
                const float b0 = bias[cc], b1 = bias[cc + 1];
                t0.x = acc[mi][ni][0] + b0; t0.y = acc[mi][ni][1] + b1;
                t1.x = acc[mi][ni][2] + b0; t1.y = acc[mi][ni][3] + b1;
            }
            *(float2*)(C + (size_t)r0 * N + cc)       = t0;
            *(float2*)(C + (size_t)(r0 + 8) * N + cc) = t1;
        }
    }
}

// ---------------------------------------------------------------------------
// Flash attention (causal), TF32 mma, cp.async loads, single-buffered KV,
// 104.4KB smem -> 2 CTAs/SM. CTA = (b, h, 128-row q-tile), 8 warps x 16 rows.
// qkv is pre-rounded (Q pre-scaled). Heavy q-tiles launch first.
// ---------------------------------------------------------------------------
#define QSTR 68

__global__ void __launch_bounds__(256, 2) attn_mma(
    const float* __restrict__ qkv, float* __restrict__ out)
{
    extern __shared__ float sm[];
    float* Qs = sm;                       // [128][QSTR]
    float* Ks = Qs + 128 * QSTR;          // [64][QSTR]
    float* Vs = Ks + 64 * QSTR;           // [64][QSTR]
    float* Ps = Vs + 64 * QSTR;           // [128][QSTR]
    const uint32_t Qs_u = smem_u32(Qs);
    const uint32_t Ks_u = smem_u32(Ks);
    const uint32_t Vs_u = smem_u32(Vs);

    const int tid  = threadIdx.x;
    const int lane = tid & 31;
    const int wid  = tid >> 5;
    const int wm   = wid * 16;
    const int qr   = lane >> 2;
    const int qc   = lane & 3;
    const int q0   = (int)(gridDim.x - 1 - blockIdx.x) * 128;  // heavy first
    const int b    = blockIdx.y >> 4;
    const int h    = blockIdx.y & 15;

    const float* base = qkv + (size_t)b * TSEQ * (3 * DM) + h * 64;

    // Q tile: 2048 float4s, 8 per thread, via cp.async
#pragma unroll
    for (int t = 0; t < 8; t++) {
        int i = tid + 256 * t;
        int row = i >> 4, d0 = (i & 15) << 2;
        CP_ASYNC16(Qs_u + ((row * QSTR + d0) << 2),
                   base + (size_t)(q0 + row) * (3 * DM) + d0);
    }

    auto ldgstsKV = [&](int k0) {
#pragma unroll
        for (int t = 0; t < 4; t++) {
            int i = tid + 256 * t;
            int key = i >> 4, d0 = (i & 15) << 2;
            const float* kp = base + DM + (size_t)(k0 + key) * (3 * DM) + d0;
            CP_ASYNC16(Ks_u + ((key * QSTR + d0) << 2), kp);
            CP_ASYNC16(Vs_u + ((key * QSTR + d0) << 2), kp + DM);
        }
        CP_COMMIT();
    };

    float oacc[8][4];
#pragma unroll
    for (int ni = 0; ni < 8; ni++)
#pragma unroll
        for (int c = 0; c < 4; c++) oacc[ni][c] = 0.f;
    float m0 = -1e30f, m1 = -1e30f, l0 = 0.f, l1 = 0.f;

    const int r0g = q0 + wm + qr;
    const int r1g = r0g + 8;
    const int ntiles = (q0 >> 6) + 2;

    ldgstsKV(0);

    for (int j = 0; j < ntiles; j++) {
        const int k0 = j << 6;
        CP_WAIT(0);
        __syncthreads();

        // ---- S = Q @ K^T ----
        float sacc[8][4];
#pragma unroll
        for (int ni = 0; ni < 8; ni++)
#pragma unroll
            for (int c = 0; c < 4; c++) sacc[ni][c] = 0.f;

#pragma unroll
        for (int kb = 0; kb < 64; kb += 8) {
            uint32_t a0 = __float_as_uint(Qs[(wm + qr) * QSTR + kb + qc]);
            uint32_t a1 = __float_as_uint(Qs[(wm + qr + 8) * QSTR + kb + qc]);
            uint32_t a2 = __float_as_uint(Qs[(wm + qr) * QSTR + kb + qc + 4]);
            uint32_t a3 = __float_as_uint(Qs[(wm + qr + 8) * QSTR + kb + qc + 4]);
#pragma unroll
            for (int ni = 0; ni < 8; ni++) {
                uint32_t b0 = __float_as_uint(Ks[(ni * 8 + qr) * QSTR + kb + qc]);
                uint32_t b1 = __float_as_uint(Ks[(ni * 8 + qr) * QSTR + kb + qc + 4]);
                mma_tf32(sacc[ni][0], sacc[ni][1], sacc[ni][2], sacc[ni][3],
                         a0, a1, a2, a3, b0, b1);
            }
        }

        // ---- online softmax ----
        const bool domask = (k0 + 63 > q0 + wm);
        float mx0 = -1e30f, mx1 = -1e30f;
#pragma unroll
        for (int ni = 0; ni < 8; ni++) {
            if (domask) {
                const int cb = k0 + ni * 8 + qc * 2;
                if (cb     > r0g) sacc[ni][0] = -1e30f;
                if (cb + 1 > r0g) sacc[ni][1] = -1e30f;
                if (cb     > r1g) sacc[ni][2] = -1e30f;
                if (cb + 1 > r1g) sacc[ni][3] = -1e30f;
            }
            mx0 = fmaxf(mx0, fmaxf(sacc[ni][0], sacc[ni][1]));
            mx1 = fmaxf(mx1, fmaxf(sacc[ni][2], sacc[ni][3]));
        }
        mx0 = fmaxf(mx0, __shfl_xor_sync(0xffffffffu, mx0, 1));
        mx0 = fmaxf(mx0, __shfl_xor_sync(0xffffffffu, mx0, 2));
        mx1 = fmaxf(mx1, __shfl_xor_sync(0xffffffffu, mx1, 1));
        mx1 = fmaxf(mx1, __shfl_xor_sync(0xffffffffu, mx1, 2));

        const float mn0 = fmaxf(m0, mx0), mn1 = fmaxf(m1, mx1);
        const float sc0 = __expf(m0 - mn0), sc1 = __expf(m1 - mn1);
        float rs0 = 0.f, rs1 = 0.f;
#pragma unroll
        for (int ni = 0; ni < 8; ni++) {
            float p0 = __expf(sacc[ni][0] - mn0);
            float p1 = __expf(sacc[ni][1] - mn0);
            float p2 = __expf(sacc[ni][2] - mn1);
            float p3 = __expf(sacc[ni][3] - mn1);
            rs0 += p0 + p1; rs1 += p2 + p3;
            float2 t0; t0.x = cvt_tf32(p0); t0.y = cvt_tf32(p1);
            float2 t1; t1.x = cvt_tf32(p2); t1.y = cvt_tf32(p3);
            *(float2*)&Ps[(wm + qr) * QSTR + ni * 8 + qc * 2]     = t0;
            *(float2*)&Ps[(wm + qr + 8) * QSTR + ni * 8 + qc * 2] = t1;
            oacc[ni][0] *= sc0; oacc[ni][1] *= sc0;
            oacc[ni][2] *= sc1; oacc[ni][3] *= sc1;
        }
        rs0 += __shfl_xor_sync(0xffffffffu, rs0, 1);
        rs0 += __shfl_xor_sync(0xffffffffu, rs0, 2);
        rs1 += __shfl_xor_sync(0xffffffffu, rs1, 1);
        rs1 += __shfl_xor_sync(0xffffffffu, rs1, 2);
        l0 = l0 * sc0 + rs0; l1 = l1 * sc1 + rs1;
        m0 = mn0; m1 = mn1;
        __syncwarp();

        // ---- O += P @ V ----
#pragma unroll
        for (int kb = 0; kb < 64; kb += 8) {
            uint32_t a0 = __float_as_uint(Ps[(wm + qr) * QSTR + kb + qc]);
            uint32_t a1 = __float_as_uint(Ps[(wm + qr + 8) * QSTR + kb + qc]);
            uint32_t a2 = __float_as_uint(Ps[(wm + qr) * QSTR + kb + qc + 4]);
            uint32_t a3 = __float_as_uint(Ps[(wm + qr + 8) * QSTR + kb + qc + 4]);
#pragma unroll
            for (int ni = 0; ni < 8; ni++) {
                uint32_t b0 = __float_as_uint(Vs[(kb + qc) * QSTR + ni * 8 + qr]);
                uint32_t b1 = __float_as_uint(Vs[(kb + qc + 4) * QSTR + ni * 8 + qr]);
                mma_tf32(oacc[ni][0], oacc[ni][1], oacc[ni][2], oacc[ni][3],
                         a0, a1, a2, a3, b0, b1);
            }
        }

        __syncthreads();   // all warps done with Ks/Vs before refill
        if (j + 1 < ntiles) ldgstsKV((j + 1) << 6);
    }

    // Normalize + write out[b, t, h*64 + d] (tf32-rounded for proj GEMM)
    const float inv0 = 1.f / l0, inv1 = 1.f / l1;
    float* o0 = out + ((size_t)b * TSEQ + r0g) * DM + h * 64;
    float* o1 = out + ((size_t)b * TSEQ + r1g) * DM + h * 64;
#pragma unroll
    for (int ni = 0; ni < 8; ni++) {
        const int cc = ni * 8 + qc * 2;
        float2 t0, t1;
        t0.x = cvt_tf32(oacc[ni][0] * inv0); t0.y = cvt_tf32(oacc[ni][1] * inv0);
        t1.x = cvt_tf32(oacc[ni][2] * inv1); t1.y = cvt_tf32(oacc[ni][3] * inv1);
        *(float2*)(o0 + cc) = t0;
        *(float2*)(o1 + cc) = t1;
    }
}

// ---------------------------------------------------------------------------
extern "C" void kernel_launch(void* const* d_in, const int* in_sizes, int n_in,
                              void* d_out, int out_size)
{
    const float* x      = (const float*)d_in[0];
    const float* w_qkv  = (const float*)d_in[1];
    const float* w_proj = (const float*)d_in[2];
    const float* b_proj = (const float*)d_in[3];
    float* out = (float*)d_out;

    float *qkv, *att, *xr, *wq, *wp;
    cudaGetSymbolAddress((void**)&qkv, g_qkv);
    cudaGetSymbolAddress((void**)&att, g_att);
    cudaGetSymbolAddress((void**)&xr,  g_xr);
    cudaGetSymbolAddress((void**)&wq,  g_wq);
    cudaGetSymbolAddress((void**)&wp,  g_wp);

    const int GSMEM = (2 * ASTG + 2 * BSTG) * 4;   // 70656 B
    cudaFuncSetAttribute(gemm_async<0>,
                         cudaFuncAttributeMaxDynamicSharedMemorySize, GSMEM);
    cudaFuncSetAttribute(gemm_async<1>,
                         cudaFuncAttributeMaxDynamicSharedMemorySize, GSMEM);
    const int ASMEM = (128 + 64 + 64 + 128) * QSTR * 4;  // 104448 B
    cudaFuncSetAttribute(attn_mma,
                         cudaFuncAttributeMaxDynamicSharedMemorySize, ASMEM);

    // 0) pre-round inputs to tf32 (rna)
    round_tf32<<<512, 256>>>((const float4*)x,      (float4*)xr, M_TOT * DM / 4);
    round_tf32<<<512, 256>>>((const float4*)w_qkv,  (float4*)wq, DM * 3 * DM / 4);
    round_tf32<<<512, 256>>>((const float4*)w_proj, (float4*)wp, DM * DM / 4);

    // 1) QKV = xr @ wq (rounded+Q-scaled at epilogue)
    gemm_async<1><<<dim3(3 * DM / 128, M_TOT / 128), 256, GSMEM>>>(
        xr, wq, nullptr, qkv, M_TOT, 3 * DM, DM);

    // 2) causal MHA -> att (rounded at write)
    attn_mma<<<dim3(TSEQ / 128, NB * 16), 256, ASMEM>>>(qkv, att);

    // 3) out = att @ wp + b_proj (fp32 epilogue)
    gemm_async<0><<<dim3(DM / 128, M_TOT / 128), 256, GSMEM>>>(
        att, wp, b_proj, out, M_TOT, DM, DM);
}

// round 7
// speedup vs baseline: 2.5707x; 2.0685x over previous
#include <cuda_runtime.h>
#include <cuda_fp16.h>
#include <cstdint>

#define TSEQ 2048
#define NB   4
#define DM   1024
#define M_TOT (NB * TSEQ)   // 8192

// Scratch (device globals: allocation-free per harness rules)
__device__ __half g_qkv[(size_t)M_TOT * 3 * DM];  // [B,T,3C] half (Q pre-scaled)
__device__ __half g_att[(size_t)M_TOT * DM];      // [B,T,C]  half
__device__ __half g_xh [(size_t)M_TOT * DM];      // half(x)
__device__ __half g_wqt[(size_t)3 * DM * DM];     // half(w_qkv)^T [3072][1024]
__device__ __half g_wpt[(size_t)DM * DM];         // half(w_proj)^T [1024][1024]

__device__ __forceinline__ uint32_t smem_u32(const void* p) {
    return (uint32_t)__cvta_generic_to_shared(p);
}
#define CP_ASYNC16(dst, src) \
    asm volatile("cp.async.cg.shared.global [%0], [%1], 16;" :: "r"(dst), "l"(src))
#define CP_COMMIT() asm volatile("cp.async.commit_group;")
#define CP_WAIT(n)  asm volatile("cp.async.wait_group %0;" :: "n"(n))
#define SWZ(o) ((o) ^ (((o) >> 3) & 0x70))

#define LDSM4(r0, r1, r2, r3, addr) \
    asm volatile("ldmatrix.sync.aligned.m8n8.x4.shared.b16 {%0,%1,%2,%3}, [%4];" \
                 : "=r"(r0), "=r"(r1), "=r"(r2), "=r"(r3) : "r"(addr))
#define LDSM4T(r0, r1, r2, r3, addr) \
    asm volatile("ldmatrix.sync.aligned.m8n8.x4.trans.shared.b16 {%0,%1,%2,%3}, [%4];" \
                 : "=r"(r0), "=r"(r1), "=r"(r2), "=r"(r3) : "r"(addr))

__device__ __forceinline__ void mma_f16(
    float& c0, float& c1, float& c2, float& c3,
    uint32_t a0, uint32_t a1, uint32_t a2, uint32_t a3,
    uint32_t b0, uint32_t b1)
{
    asm volatile(
        "mma.sync.aligned.m16n8k16.row.col.f32.f16.f16.f32 "
        "{%0,%1,%2,%3}, {%4,%5,%6,%7}, {%8,%9}, {%0,%1,%2,%3};"
        : "+f"(c0), "+f"(c1), "+f"(c2), "+f"(c3)
        : "r"(a0), "r"(a1), "r"(a2), "r"(a3), "r"(b0), "r"(b1));
}

__device__ __forceinline__ uint32_t packh2(float a, float b) {
    __half2 h = __floats2half2_rn(a, b);
    return *(uint32_t*)&h;
}

// ---------------------------------------------------------------------------
// Pre-pass: fp32 -> half; fp32 -> half transposed [N][K]
// ---------------------------------------------------------------------------
__global__ void f32_to_h(const float4* __restrict__ in,
                         uint2* __restrict__ out, int n4)
{
    int i = blockIdx.x * blockDim.x + threadIdx.x;
    int st = gridDim.x * blockDim.x;
    for (; i < n4; i += st) {
        float4 v = in[i];
        uint2 r;
        r.x = packh2(v.x, v.y);
        r.y = packh2(v.z, v.w);
        out[i] = r;
    }
}

__global__ void transpose_h(const float* __restrict__ in,
                            __half* __restrict__ out, int K, int N)
{
    __shared__ float t[32][33];
    const int n0 = blockIdx.x * 32, k0 = blockIdx.y * 32;
#pragma unroll
    for (int i = 0; i < 4; i++)
        t[threadIdx.y + 8 * i][threadIdx.x] =
            in[(size_t)(k0 + threadIdx.y + 8 * i) * N + n0 + threadIdx.x];
    __syncthreads();
#pragma unroll
    for (int i = 0; i < 4; i++)
        out[(size_t)(n0 + threadIdx.y + 8 * i) * K + k0 + threadIdx.x] =
            __float2half_rn(t[threadIdx.x][threadIdx.y + 8 * i]);
}

// ---------------------------------------------------------------------------
// fp16 HMMA GEMM: C[M,N] = A[M,K] @ Bt[N,K]^T (+bias / epilogue)
// 128x128 CTA, BK=64, 256 threads, 8 warps (2x4) of 64x32. m16n8k16.
// SW128-swizzled half tiles, cp.async double buffer, ldmatrix fragments.
// EPI=1: half out, cols<DM scaled 0.125 (qkv).  EPI=0: fp32 out + bias.
// ---------------------------------------------------------------------------
#define GSTG 32768   // bytes per stage: A 16KB + B 16KB

template <int EPI>
__global__ void __launch_bounds__(256, 2) gemm_h(
    const __half* __restrict__ A, const __half* __restrict__ Bt,
    const float* __restrict__ bias, void* __restrict__ Cv,
    int N, int K)
{
    extern __shared__ char smem[];
    const uint32_t smem_u = smem_u32(smem);

    const int tid  = threadIdx.x;
    const int lane = tid & 31;
    const int wid  = tid >> 5;
    const int wm   = (wid & 1) * 64;
    const int wn   = (wid >> 1) * 32;
    const int bm   = blockIdx.y * 128;
    const int bn   = blockIdx.x * 128;
    const int qr   = lane >> 2;
    const int qc   = lane & 3;
    const int lrow = tid >> 1;
    const int lcp  = (tid & 1) * 4;

    float acc[4][4][4];
#pragma unroll
    for (int mi = 0; mi < 4; mi++)
#pragma unroll
        for (int ni = 0; ni < 4; ni++)
#pragma unroll
            for (int c = 0; c < 4; c++) acc[mi][ni][c] = 0.f;

    auto ldgsts = [&](int stage, int s) {
        const int k0 = s << 6;
        const uint32_t su = smem_u + stage * GSTG;
#pragma unroll
        for (int c = 0; c < 4; c++) {
            const int ch = lcp + c;
            const uint32_t o = lrow * 128 + ch * 16;
            CP_ASYNC16(su + SWZ(o),         A  + (size_t)(bm + lrow) * K + k0 + ch * 8);
            CP_ASYNC16(su + 16384 + SWZ(o), Bt + (size_t)(bn + lrow) * K + k0 + ch * 8);
        }
        CP_COMMIT();
    };

    auto compute = [&](int stage) {
        const uint32_t Au = smem_u + stage * GSTG;
        const uint32_t Bu = Au + 16384;
#pragma unroll
        for (int ks = 0; ks < 4; ks++) {
            const int kb = ks * 16;
            uint32_t af[4][4], bf[4][2];
#pragma unroll
            for (int mi = 0; mi < 4; mi++) {
                const int row = wm + mi * 16 + (lane & 15);
                const int h   = kb + ((lane >> 4) << 3);
                const uint32_t ad = Au + row * 128 + ((((h >> 3) ^ row) & 7) << 4)
                                    + ((h >> 3) & ~7) * 16;
                LDSM4(af[mi][0], af[mi][1], af[mi][2], af[mi][3], ad);
            }
#pragma unroll
            for (int p = 0; p < 2; p++) {
                const int row = wn + p * 16 + ((lane >> 4) << 3) + (lane & 7);
                const int h   = kb + (((lane >> 3) & 1) << 3);
                const uint32_t ad = Bu + row * 128 + ((((h >> 3) ^ row) & 7) << 4)
                                    + ((h >> 3) & ~7) * 16;
                LDSM4(bf[2*p][0], bf[2*p][1], bf[2*p+1][0], bf[2*p+1][1], ad);
            }
#pragma unroll
            for (int mi = 0; mi < 4; mi++)
#pragma unroll
                for (int ni = 0; ni < 4; ni++)
                    mma_f16(acc[mi][ni][0], acc[mi][ni][1],
                            acc[mi][ni][2], acc[mi][ni][3],
                            af[mi][0], af[mi][1], af[mi][2], af[mi][3],
                            bf[ni][0], bf[ni][1]);
        }
    };

    const int nslab = K >> 6;   // 16
    ldgsts(0, 0);
    ldgsts(1, 1);

    for (int s = 0; s < nslab; s++) {
        CP_WAIT(1);
        __syncthreads();
        compute(s & 1);
        __syncthreads();
        if (s + 2 < nslab) ldgsts(s & 1, s + 2);
        else               CP_COMMIT();
    }

    // epilogue
#pragma unroll
    for (int mi = 0; mi < 4; mi++) {
        const int r0 = bm + wm + mi * 16 + qr;
#pragma unroll
        for (int ni = 0; ni < 4; ni++) {
            const int cc = bn + wn + ni * 8 + qc * 2;
            if (EPI == 1) {
                __half* C = (__half*)Cv;
                const float cs = (cc < DM) ? 0.125f : 1.0f;
                *(__half2*)(C + (size_t)r0 * N + cc) =
                    __floats2half2_rn(acc[mi][ni][0] * cs, acc[mi][ni][1] * cs);
                *(__half2*)(C + (size_t)(r0 + 8) * N + cc) =
                    __floats2half2_rn(acc[mi][ni][2] * cs, acc[mi][ni][3] * cs);
            } else {
                float* C = (float*)Cv;
                const float b0 = bias[cc], b1 = bias[cc + 1];
                float2 t0, t1;
                t0.x = acc[mi][ni][0] + b0; t0.y = acc[mi][ni][1] + b1;
                t1.x = acc[mi][ni][2] + b0; t1.y = acc[mi][ni][3] + b1;
                *(float2*)(C + (size_t)r0 * N + cc)       = t0;
                *(float2*)(C + (size_t)(r0 + 8) * N + cc) = t1;
            }
        }
    }
}

// ---------------------------------------------------------------------------
// Flash attention (causal), fp16 m16n8k16, ldmatrix, P kept in registers.
// CTA = (b, h, 128-row q-tile), 8 warps x 16 rows, BC=64 keys. Smem 32KB.
// qkv half, Q pre-scaled. Output att half.
// ---------------------------------------------------------------------------
__global__ void __launch_bounds__(256, 2) attn_h(
    const __half* __restrict__ qkv, __half* __restrict__ out)
{
    extern __shared__ char sm[];
    const uint32_t Qu = smem_u32(sm);        // [128][64] half, 16KB
    const uint32_t Ku = Qu + 16384;          // [64][64]  half,  8KB
    const uint32_t Vu = Ku + 8192;           // [64][64]  half,  8KB

    const int tid  = threadIdx.x;
    const int lane = tid & 31;
    const int wid  = tid >> 5;
    const int wm   = wid * 16;
    const int qr   = lane >> 2;
    const int qc   = lane & 3;
    const int q0   = (int)(gridDim.x - 1 - blockIdx.x) * 128;  // heavy first
    const int b    = blockIdx.y >> 4;
    const int h    = blockIdx.y & 15;

    const __half* base = qkv + (size_t)b * TSEQ * (3 * DM) + h * 64;

    // Q tile via cp.async (committed with first KV group)
    {
        const int row = tid >> 1;
#pragma unroll
        for (int c = 0; c < 4; c++) {
            const int ch = (tid & 1) * 4 + c;
            const uint32_t o = row * 128 + ch * 16;
            CP_ASYNC16(Qu + SWZ(o), base + (size_t)(q0 + row) * (3 * DM) + ch * 8);
        }
    }

    auto ldgstsKV = [&](int k0) {
        const int row = tid >> 2;
        const __half* kp = base + DM + (size_t)(k0 + row) * (3 * DM);
#pragma unroll
        for (int c = 0; c < 2; c++) {
            const int ch = (tid & 3) * 2 + c;
            const uint32_t o = row * 128 + ch * 16;
            CP_ASYNC16(Ku + SWZ(o), kp + ch * 8);
            CP_ASYNC16(Vu + SWZ(o), kp + DM + ch * 8);
        }
        CP_COMMIT();
    };

    float oacc[8][4];
#pragma unroll
    for (int ni = 0; ni < 8; ni++)
#pragma unroll
        for (int c = 0; c < 4; c++) oacc[ni][c] = 0.f;
    float m0 = -1e30f, m1 = -1e30f, l0 = 0.f, l1 = 0.f;

    const int r0g = q0 + wm + qr;
    const int r1g = r0g + 8;
    const int ntiles = (q0 >> 6) + 2;

    ldgstsKV(0);

    for (int j = 0; j < ntiles; j++) {
        const int k0 = j << 6;
        CP_WAIT(0);
        __syncthreads();

        // ---- S = Q @ K^T ----
        float sacc[8][4];
#pragma unroll
        for (int ni = 0; ni < 8; ni++)
#pragma unroll
            for (int c = 0; c < 4; c++) sacc[ni][c] = 0.f;

#pragma unroll
        for (int ks = 0; ks < 4; ks++) {
            const int kb = ks * 16;
            uint32_t aq[4];
            {
                const int row = wm + (lane & 15);
                const int hh  = kb + ((lane >> 4) << 3);
                const uint32_t ad = Qu + row * 128 + ((((hh >> 3) ^ row) & 7) << 4)
                                    + ((hh >> 3) & ~7) * 16;
                LDSM4(aq[0], aq[1], aq[2], aq[3], ad);
            }
            uint32_t bk[8][2];
#pragma unroll
            for (int p = 0; p < 4; p++) {
                const int row = p * 16 + ((lane >> 4) << 3) + (lane & 7);
                const int hh  = kb + (((lane >> 3) & 1) << 3);
                const uint32_t ad = Ku + row * 128 + ((((hh >> 3) ^ row) & 7) << 4)
                                    + ((hh >> 3) & ~7) * 16;
                LDSM4(bk[2*p][0], bk[2*p][1], bk[2*p+1][0], bk[2*p+1][1], ad);
            }
#pragma unroll
            for (int ni = 0; ni < 8; ni++)
                mma_f16(sacc[ni][0], sacc[ni][1], sacc[ni][2], sacc[ni][3],
                        aq[0], aq[1], aq[2], aq[3], bk[ni][0], bk[ni][1]);
        }

        // ---- online softmax (C-fragment layout) ----
        const bool domask = (k0 + 63 > q0 + wm);
        float mx0 = -1e30f, mx1 = -1e30f;
#pragma unroll
        for (int ni = 0; ni < 8; ni++) {
            if (domask) {
                const int cb = k0 + ni * 8 + qc * 2;
                if (cb     > r0g) sacc[ni][0] = -1e30f;
                if (cb + 1 > r0g) sacc[ni][1] = -1e30f;
                if (cb     > r1g) sacc[ni][2] = -1e30f;
                if (cb + 1 > r1g) sacc[ni][3] = -1e30f;
            }
            mx0 = fmaxf(mx0, fmaxf(sacc[ni][0], sacc[ni][1]));
            mx1 = fmaxf(mx1, fmaxf(sacc[ni][2], sacc[ni][3]));
        }
        mx0 = fmaxf(mx0, __shfl_xor_sync(0xffffffffu, mx0, 1));
        mx0 = fmaxf(mx0, __shfl_xor_sync(0xffffffffu, mx0, 2));
        mx1 = fmaxf(mx1, __shfl_xor_sync(0xffffffffu, mx1, 1));
        mx1 = fmaxf(mx1, __shfl_xor_sync(0xffffffffu, mx1, 2));

        const float mn0 = fmaxf(m0, mx0), mn1 = fmaxf(m1, mx1);
        const float sc0 = __expf(m0 - mn0), sc1 = __expf(m1 - mn1);
        float rs0 = 0.f, rs1 = 0.f;
        uint32_t ph[8][2];
#pragma unroll
        for (int ni = 0; ni < 8; ni++) {
            float p0 = __expf(sacc[ni][0] - mn0);
            float p1 = __expf(sacc[ni][1] - mn0);
            float p2 = __expf(sacc[ni][2] - mn1);
            float p3 = __expf(sacc[ni][3] - mn1);
            rs0 += p0 + p1; rs1 += p2 + p3;
            ph[ni][0] = packh2(p0, p1);
            ph[ni][1] = packh2(p2, p3);
            oacc[ni][0] *= sc0; oacc[ni][1] *= sc0;
            oacc[ni][2] *= sc1; oacc[ni][3] *= sc1;
        }
        rs0 += __shfl_xor_sync(0xffffffffu, rs0, 1);
        rs0 += __shfl_xor_sync(0xffffffffu, rs0, 2);
        rs1 += __shfl_xor_sync(0xffffffffu, rs1, 1);
        rs1 += __shfl_xor_sync(0xffffffffu, rs1, 2);
        l0 = l0 * sc0 + rs0; l1 = l1 * sc1 + rs1;
        m0 = mn0; m1 = mn1;

        // ---- O += P @ V (P from registers, V via ldmatrix.trans) ----
#pragma unroll
        for (int s2 = 0; s2 < 4; s2++) {
            const int kb = s2 * 16;
            uint32_t vb[8][2];
#pragma unroll
            for (int p = 0; p < 4; p++) {
                const int row = kb + (((lane >> 3) & 1) << 3) + (lane & 7);
                const int hh  = p * 16 + ((lane >> 4) << 3);
                const uint32_t ad = Vu + row * 128 + ((((hh >> 3) ^ row) & 7) << 4)
                                    + ((hh >> 3) & ~7) * 16;
                LDSM4T(vb[2*p][0], vb[2*p][1], vb[2*p+1][0], vb[2*p+1][1], ad);
            }
            const uint32_t a0 = ph[2*s2][0], a1 = ph[2*s2][1];
            const uint32_t a2 = ph[2*s2+1][0], a3 = ph[2*s2+1][1];
#pragma unroll
            for (int ni = 0; ni < 8; ni++)
                mma_f16(oacc[ni][0], oacc[ni][1], oacc[ni][2], oacc[ni][3],
                        a0, a1, a2, a3, vb[ni][0], vb[ni][1]);
        }

        __syncthreads();   // all warps done with Ks/Vs before refill
        if (j + 1 < ntiles) ldgstsKV((j + 1) << 6);
    }

    // Normalize + write att[b, t, h*64 + d] as half
    const float inv0 = 1.f / l0, inv1 = 1.f / l1;
    __half* o0 = out + ((size_t)b * TSEQ + r0g) * DM + h * 64;
    __half* o1 = out + ((size_t)b * TSEQ + r1g) * DM + h * 64;
#pragma unroll
    for (int ni = 0; ni < 8; ni++) {
        const int cc = ni * 8 + qc * 2;
        *(__half2*)(o0 + cc) = __floats2half2_rn(oacc[ni][0] * inv0, oacc[ni][1] * inv0);
        *(__half2*)(o1 + cc) = __floats2half2_rn(oacc[ni][2] * inv1, oacc[ni][3] * inv1);
    }
}

// ---------------------------------------------------------------------------
extern "C" void kernel_launch(void* const* d_in, const int* in_sizes, int n_in,
                              void* d_out, int out_size)
{
    const float* x      = (const float*)d_in[0];
    const float* w_qkv  = (const float*)d_in[1];
    const float* w_proj = (const float*)d_in[2];
    const float* b_proj = (const float*)d_in[3];
    float* out = (float*)d_out;

    __half *qkv, *att, *xh, *wqt, *wpt;
    cudaGetSymbolAddress((void**)&qkv, g_qkv);
    cudaGetSymbolAddress((void**)&att, g_att);
    cudaGetSymbolAddress((void**)&xh,  g_xh);
    cudaGetSymbolAddress((void**)&wqt, g_wqt);
    cudaGetSymbolAddress((void**)&wpt, g_wpt);

    const int GSMEM = 2 * GSTG;                 // 65536
    cudaFuncSetAttribute(gemm_h<1>,
                         cudaFuncAttributeMaxDynamicSharedMemorySize, GSMEM);
    cudaFuncSetAttribute(gemm_h<0>,
                         cudaFuncAttributeMaxDynamicSharedMemorySize, GSMEM);
    const int ASMEM = 16384 + 8192 + 8192;      // 32768
    cudaFuncSetAttribute(attn_h,
                         cudaFuncAttributeMaxDynamicSharedMemorySize, ASMEM);

    // 0) pre-pass: x -> half; weights -> half transposed [N][K]
    f32_to_h<<<512, 256>>>((const float4*)x, (uint2*)xh, M_TOT * DM / 4);
    transpose_h<<<dim3(3 * DM / 32, DM / 32), dim3(32, 8)>>>(w_qkv, wqt, DM, 3 * DM);
    transpose_h<<<dim3(DM / 32, DM / 32), dim3(32, 8)>>>(w_proj, wpt, DM, DM);

    // 1) QKV = xh @ wqt^T  (8192 x 3072 x 1024), fp16 HMMA, half out (Q scaled)
    gemm_h<1><<<dim3(3 * DM / 128, M_TOT / 128), 256, GSMEM>>>(
        xh, wqt, nullptr, qkv, 3 * DM, DM);

    // 2) causal MHA -> att (half)
    attn_h<<<dim3(TSEQ / 128, NB * 16), 256, ASMEM>>>(qkv, att);

    // 3) out = att @ wpt^T + b_proj  (8192 x 1024 x 1024), fp32 out
    gemm_h<0><<<dim3(DM / 128, M_TOT / 128), 256, GSMEM>>>(
        att, wpt, b_proj, out, DM, DM);
}

// round 8
// speedup vs baseline: 2.5959x; 1.0098x over previous
#include <cuda_runtime.h>
#include <cuda_fp16.h>
#include <cstdint>

#define TSEQ 2048
#define NB   4
#define DM   1024
#define M_TOT (NB * TSEQ)   // 8192

// Scratch (device globals: allocation-free per harness rules)
__device__ __half g_qkv[(size_t)M_TOT * 3 * DM];  // [B,T,3C] half (Q pre-scaled)
__device__ __half g_att[(size_t)M_TOT * DM];      // [B,T,C]  half
__device__ __half g_xh [(size_t)M_TOT * DM];      // half(x)
__device__ __half g_wqt[(size_t)3 * DM * DM];     // half(w_qkv)^T [3072][1024]
__device__ __half g_wpt[(size_t)DM * DM];         // half(w_proj)^T [1024][1024]

__device__ __forceinline__ uint32_t smem_u32(const void* p) {
    return (uint32_t)__cvta_generic_to_shared(p);
}
#define CP_ASYNC16(dst, src) \
    asm volatile("cp.async.cg.shared.global [%0], [%1], 16;" :: "r"(dst), "l"(src))
#define CP_COMMIT() asm volatile("cp.async.commit_group;")
#define CP_WAIT(n)  asm volatile("cp.async.wait_group %0;" :: "n"(n))
#define SWZ(o) ((o) ^ (((o) >> 3) & 0x70))

#define LDSM4(r0, r1, r2, r3, addr) \
    asm volatile("ldmatrix.sync.aligned.m8n8.x4.shared.b16 {%0,%1,%2,%3}, [%4];" \
                 : "=r"(r0), "=r"(r1), "=r"(r2), "=r"(r3) : "r"(addr))
#define LDSM4T(r0, r1, r2, r3, addr) \
    asm volatile("ldmatrix.sync.aligned.m8n8.x4.trans.shared.b16 {%0,%1,%2,%3}, [%4];" \
                 : "=r"(r0), "=r"(r1), "=r"(r2), "=r"(r3) : "r"(addr))

__device__ __forceinline__ void mma_f16(
    float& c0, float& c1, float& c2, float& c3,
    uint32_t a0, uint32_t a1, uint32_t a2, uint32_t a3,
    uint32_t b0, uint32_t b1)
{
    asm volatile(
        "mma.sync.aligned.m16n8k16.row.col.f32.f16.f16.f32 "
        "{%0,%1,%2,%3}, {%4,%5,%6,%7}, {%8,%9}, {%0,%1,%2,%3};"
        : "+f"(c0), "+f"(c1), "+f"(c2), "+f"(c3)
        : "r"(a0), "r"(a1), "r"(a2), "r"(a3), "r"(b0), "r"(b1));
}

__device__ __forceinline__ uint32_t packh2(float a, float b) {
    __half2 h = __floats2half2_rn(a, b);
    return *(uint32_t*)&h;
}

// ---------------------------------------------------------------------------
// Pre-pass: fp32 -> half; fp32 -> half transposed [N][K]
// ---------------------------------------------------------------------------
__global__ void f32_to_h(const float4* __restrict__ in,
                         uint2* __restrict__ out, int n4)
{
    int i = blockIdx.x * blockDim.x + threadIdx.x;
    int st = gridDim.x * blockDim.x;
    for (; i < n4; i += st) {
        float4 v = in[i];
        uint2 r;
        r.x = packh2(v.x, v.y);
        r.y = packh2(v.z, v.w);
        out[i] = r;
    }
}

__global__ void transpose_h(const float* __restrict__ in,
                            __half* __restrict__ out, int K, int N)
{
    __shared__ float t[32][33];
    const int n0 = blockIdx.x * 32, k0 = blockIdx.y * 32;
#pragma unroll
    for (int i = 0; i < 4; i++)
        t[threadIdx.y + 8 * i][threadIdx.x] =
            in[(size_t)(k0 + threadIdx.y + 8 * i) * N + n0 + threadIdx.x];
    __syncthreads();
#pragma unroll
    for (int i = 0; i < 4; i++)
        out[(size_t)(n0 + threadIdx.y + 8 * i) * K + k0 + threadIdx.x] =
            __float2half_rn(t[threadIdx.x][threadIdx.y + 8 * i]);
}

// ---------------------------------------------------------------------------
// fp16 HMMA GEMM: C[M,N] = A[M,K] @ Bt[N,K]^T (+bias / epilogue)
// 128x128 CTA, BK=64, 256 threads, 8 warps (2x4) of 64x32. m16n8k16.
// SW128-swizzled half tiles, 3-stage cp.async ring (1 barrier/slab,
// loads issued before compute). ldmatrix fragments.
// EPI=1: half out, cols<DM scaled 0.125 (qkv).  EPI=0: fp32 out + bias.
// ---------------------------------------------------------------------------
#define GSTG 32768   // bytes per stage: A 16KB + B 16KB

template <int EPI>
__global__ void __launch_bounds__(256, 2) gemm_h(
    const __half* __restrict__ A, const __half* __restrict__ Bt,
    const float* __restrict__ bias, void* __restrict__ Cv,
    int N, int K)
{
    extern __shared__ char smem[];
    const uint32_t smem_u = smem_u32(smem);

    const int tid  = threadIdx.x;
    const int lane = tid & 31;
    const int wid  = tid >> 5;
    const int wm   = (wid & 1) * 64;
    const int wn   = (wid >> 1) * 32;
    const int bm   = blockIdx.y * 128;
    const int bn   = blockIdx.x * 128;
    const int qr   = lane >> 2;
    const int qc   = lane & 3;
    const int lrow = tid >> 1;
    const int lcp  = (tid & 1) * 4;

    float acc[4][4][4];
#pragma unroll
    for (int mi = 0; mi < 4; mi++)
#pragma unroll
        for (int ni = 0; ni < 4; ni++)
#pragma unroll
            for (int c = 0; c < 4; c++) acc[mi][ni][c] = 0.f;

    auto ldgsts = [&](int stage, int s) {
        const int k0 = s << 6;
        const uint32_t su = smem_u + stage * GSTG;
#pragma unroll
        for (int c = 0; c < 4; c++) {
            const int ch = lcp + c;
            const uint32_t o = lrow * 128 + ch * 16;
            CP_ASYNC16(su + SWZ(o),         A  + (size_t)(bm + lrow) * K + k0 + ch * 8);
            CP_ASYNC16(su + 16384 + SWZ(o), Bt + (size_t)(bn + lrow) * K + k0 + ch * 8);
        }
        CP_COMMIT();
    };

    auto compute = [&](int stage) {
        const uint32_t Au = smem_u + stage * GSTG;
        const uint32_t Bu = Au + 16384;
#pragma unroll
        for (int ks = 0; ks < 4; ks++) {
            const int kb = ks * 16;
            uint32_t af[4][4], bf[4][2];
#pragma unroll
            for (int mi = 0; mi < 4; mi++) {
                const int row = wm + mi * 16 + (lane & 15);
                const int h   = kb + ((lane >> 4) << 3);
                const uint32_t ad = Au + row * 128 + ((((h >> 3) ^ row) & 7) << 4)
                                    + ((h >> 3) & ~7) * 16;
                LDSM4(af[mi][0], af[mi][1], af[mi][2], af[mi][3], ad);
            }
#pragma unroll
            for (int p = 0; p < 2; p++) {
                const int row = wn + p * 16 + ((lane >> 4) << 3) + (lane & 7);
                const int h   = kb + (((lane >> 3) & 1) << 3);
                const uint32_t ad = Bu + row * 128 + ((((h >> 3) ^ row) & 7) << 4)
                                    + ((h >> 3) & ~7) * 16;
                LDSM4(bf[2*p][0], bf[2*p][1], bf[2*p+1][0], bf[2*p+1][1], ad);
            }
#pragma unroll
            for (int mi = 0; mi < 4; mi++)
#pragma unroll
                for (int ni = 0; ni < 4; ni++)
                    mma_f16(acc[mi][ni][0], acc[mi][ni][1],
                            acc[mi][ni][2], acc[mi][ni][3],
                            af[mi][0], af[mi][1], af[mi][2], af[mi][3],
                            bf[ni][0], bf[ni][1]);
        }
    };

    const int nslab = K >> 6;   // 16
    ldgsts(0, 0);
    ldgsts(1, 1);

    for (int s = 0; s < nslab; s++) {
        CP_WAIT(1);
        __syncthreads();
        // issue next loads BEFORE compute: stage (s+2)%3 was last read at s-1,
        // protected by the barrier above.
        if (s + 2 < nslab) ldgsts((s + 2) % 3, s + 2);
        else               CP_COMMIT();
        compute(s % 3);
    }

    // epilogue
#pragma unroll
    for (int mi = 0; mi < 4; mi++) {
        const int r0 = bm + wm + mi * 16 + qr;
#pragma unroll
        for (int ni = 0; ni < 4; ni++) {
            const int cc = bn + wn + ni * 8 + qc * 2;
            if (EPI == 1) {
                __half* C = (__half*)Cv;
                const float cs = (cc < DM) ? 0.125f : 1.0f;
                *(__half2*)(C + (size_t)r0 * N + cc) =
                    __floats2half2_rn(acc[mi][ni][0] * cs, acc[mi][ni][1] * cs);
                *(__half2*)(C + (size_t)(r0 + 8) * N + cc) =
                    __floats2half2_rn(acc[mi][ni][2] * cs, acc[mi][ni][3] * cs);
            } else {
                float* C = (float*)Cv;
                const float b0 = bias[cc], b1 = bias[cc + 1];
                float2 t0, t1;
                t0.x = acc[mi][ni][0] + b0; t0.y = acc[mi][ni][1] + b1;
                t1.x = acc[mi][ni][2] + b0; t1.y = acc[mi][ni][3] + b1;
                *(float2*)(C + (size_t)r0 * N + cc)       = t0;
                *(float2*)(C + (size_t)(r0 + 8) * N + cc) = t1;
            }
        }
    }
}

// ---------------------------------------------------------------------------
// Flash attention (causal), fp16 m16n8k16, ldmatrix, P in registers.
// CTA = (b, h, 128-row q-tile), 8 warps x 16 rows, BC=64 keys.
// 3-stage KV ring via cp.async (1 barrier per tile, loads before compute).
// Smem: Q 16KB + 3 x (K 8KB + V 8KB) = 64KB -> 2 CTAs/SM.
// ---------------------------------------------------------------------------
#define KVSTG 16384

__global__ void __launch_bounds__(256, 2) attn_h(
    const __half* __restrict__ qkv, __half* __restrict__ out)
{
    extern __shared__ char sm[];
    const uint32_t Qu  = smem_u32(sm);        // [128][64] half, 16KB
    const uint32_t KV0 = Qu + 16384;          // 3 stages of K(8KB)+V(8KB)

    const int tid  = threadIdx.x;
    const int lane = tid & 31;
    const int wid  = tid >> 5;
    const int wm   = wid * 16;
    const int qr   = lane >> 2;
    const int qc   = lane & 3;
    const int q0   = (int)(gridDim.x - 1 - blockIdx.x) * 128;  // heavy first
    const int b    = blockIdx.y >> 4;
    const int h    = blockIdx.y & 15;

    const __half* base = qkv + (size_t)b * TSEQ * (3 * DM) + h * 64;

    // Q tile via cp.async (joins first KV commit group)
    {
        const int row = tid >> 1;
#pragma unroll
        for (int c = 0; c < 4; c++) {
            const int ch = (tid & 1) * 4 + c;
            const uint32_t o = row * 128 + ch * 16;
            CP_ASYNC16(Qu + SWZ(o), base + (size_t)(q0 + row) * (3 * DM) + ch * 8);
        }
    }

    auto ldgstsKV = [&](int stage, int k0) {
        const uint32_t Ku = KV0 + stage * KVSTG;
        const uint32_t Vu = Ku + 8192;
        const int row = tid >> 2;
        const __half* kp = base + DM + (size_t)(k0 + row) * (3 * DM);
#pragma unroll
        for (int c = 0; c < 2; c++) {
            const int ch = (tid & 3) * 2 + c;
            const uint32_t o = row * 128 + ch * 16;
            CP_ASYNC16(Ku + SWZ(o), kp + ch * 8);
            CP_ASYNC16(Vu + SWZ(o), kp + DM + ch * 8);
        }
        CP_COMMIT();
    };

    float oacc[8][4];
#pragma unroll
    for (int ni = 0; ni < 8; ni++)
#pragma unroll
        for (int c = 0; c < 4; c++) oacc[ni][c] = 0.f;
    float m0 = -1e30f, m1 = -1e30f, l0 = 0.f, l1 = 0.f;

    const int r0g = q0 + wm + qr;
    const int r1g = r0g + 8;
    const int ntiles = (q0 >> 6) + 2;

    ldgstsKV(0, 0);          // group 0: Q + KV tile 0
    ldgstsKV(1, 64);         // group 1: KV tile 1 (ntiles >= 2 always)

    for (int j = 0; j < ntiles; j++) {
        const int k0 = j << 6;
        CP_WAIT(1);
        __syncthreads();
        if (j + 2 < ntiles) ldgstsKV((j + 2) % 3, (j + 2) << 6);
        else                CP_COMMIT();

        const uint32_t Ku = KV0 + (j % 3) * KVSTG;
        const uint32_t Vu = Ku + 8192;

        // ---- S = Q @ K^T ----
        float sacc[8][4];
#pragma unroll
        for (int ni = 0; ni < 8; ni++)
#pragma unroll
            for (int c = 0; c < 4; c++) sacc[ni][c] = 0.f;

#pragma unroll
        for (int ks = 0; ks < 4; ks++) {
            const int kb = ks * 16;
            uint32_t aq[4];
            {
                const int row = wm + (lane & 15);
                const int hh  = kb + ((lane >> 4) << 3);
                const uint32_t ad = Qu + row * 128 + ((((hh >> 3) ^ row) & 7) << 4)
                                    + ((hh >> 3) & ~7) * 16;
                LDSM4(aq[0], aq[1], aq[2], aq[3], ad);
            }
            uint32_t bk[8][2];
#pragma unroll
            for (int p = 0; p < 4; p++) {
                const int row = p * 16 + ((lane >> 4) << 3) + (lane & 7);
                const int hh  = kb + (((lane >> 3) & 1) << 3);
                const uint32_t ad = Ku + row * 128 + ((((hh >> 3) ^ row) & 7) << 4)
                                    + ((hh >> 3) & ~7) * 16;
                LDSM4(bk[2*p][0], bk[2*p][1], bk[2*p+1][0], bk[2*p+1][1], ad);
            }
#pragma unroll
            for (int ni = 0; ni < 8; ni++)
                mma_f16(sacc[ni][0], sacc[ni][1], sacc[ni][2], sacc[ni][3],
                        aq[0], aq[1], aq[2], aq[3], bk[ni][0], bk[ni][1]);
        }

        // ---- online softmax (C-fragment layout) ----
        const bool domask = (k0 + 63 > q0 + wm);
        float mx0 = -1e30f, mx1 = -1e30f;
#pragma unroll
        for (int ni = 0; ni < 8; ni++) {
            if (domask) {
                const int cb = k0 + ni * 8 + qc * 2;
                if (cb     > r0g) sacc[ni][0] = -1e30f;
                if (cb + 1 > r0g) sacc[ni][1] = -1e30f;
                if (cb     > r1g) sacc[ni][2] = -1e30f;
                if (cb + 1 > r1g) sacc[ni][3] = -1e30f;
            }
            mx0 = fmaxf(mx0, fmaxf(sacc[ni][0], sacc[ni][1]));
            mx1 = fmaxf(mx1, fmaxf(sacc[ni][2], sacc[ni][3]));
        }
        mx0 = fmaxf(mx0, __shfl_xor_sync(0xffffffffu, mx0, 1));
        mx0 = fmaxf(mx0, __shfl_xor_sync(0xffffffffu, mx0, 2));
        mx1 = fmaxf(mx1, __shfl_xor_sync(0xffffffffu, mx1, 1));
        mx1 = fmaxf(mx1, __shfl_xor_sync(0xffffffffu, mx1, 2));

        const float mn0 = fmaxf(m0, mx0), mn1 = fmaxf(m1, mx1);
        const float sc0 = __expf(m0 - mn0), sc1 = __expf(m1 - mn1);
        float rs0 = 0.f, rs1 = 0.f;
        uint32_t ph[8][2];
#pragma unroll
        for (int ni = 0; ni < 8; ni++) {
            float p0 = __expf(sacc[ni][0] - mn0);
            float p1 = __expf(sacc[ni][1] - mn0);
            float p2 = __expf(sacc[ni][2] - mn1);
            float p3 = __expf(sacc[ni][3] - mn1);
            rs0 += p0 + p1; rs1 += p2 + p3;
            ph[ni][0] = packh2(p0, p1);
            ph[ni][1] = packh2(p2, p3);
            oacc[ni][0] *= sc0; oacc[ni][1] *= sc0;
            oacc[ni][2] *= sc1; oacc[ni][3] *= sc1;
        }
        rs0 += __shfl_xor_sync(0xffffffffu, rs0, 1);
        rs0 += __shfl_xor_sync(0xffffffffu, rs0, 2);
        rs1 += __shfl_xor_sync(0xffffffffu, rs1, 1);
        rs1 += __shfl_xor_sync(0xffffffffu, rs1, 2);
        l0 = l0 * sc0 + rs0; l1 = l1 * sc1 + rs1;
        m0 = mn0; m1 = mn1;

        // ---- O += P @ V (P from registers, V via ldmatrix.trans) ----
#pragma unroll
        for (int s2 = 0; s2 < 4; s2++) {
            const int kb = s2 * 16;
            uint32_t vb[8][2];
#pragma unroll
            for (int p = 0; p < 4; p++) {
                const int row = kb + (((lane >> 3) & 1) << 3) + (lane & 7);
                const int hh  = p * 16 + ((lane >> 4) << 3);
                const uint32_t ad = Vu + row * 128 + ((((hh >> 3) ^ row) & 7) << 4)
                                    + ((hh >> 3) & ~7) * 16;
                LDSM4T(vb[2*p][0], vb[2*p][1], vb[2*p+1][0], vb[2*p+1][1], ad);
            }
            const uint32_t a0 = ph[2*s2][0], a1 = ph[2*s2][1];
            const uint32_t a2 = ph[2*s2+1][0], a3 = ph[2*s2+1][1];
#pragma unroll
            for (int ni = 0; ni < 8; ni++)
                mma_f16(oacc[ni][0], oacc[ni][1], oacc[ni][2], oacc[ni][3],
                        a0, a1, a2, a3, vb[ni][0], vb[ni][1]);
        }
    }

    // Normalize + write att[b, t, h*64 + d] as half
    const float inv0 = 1.f / l0, inv1 = 1.f / l1;
    __half* o0 = out + ((size_t)b * TSEQ + r0g) * DM + h * 64;
    __half* o1 = out + ((size_t)b * TSEQ + r1g) * DM + h * 64;
#pragma unroll
    for (int ni = 0; ni < 8; ni++) {
        const int cc = ni * 8 + qc * 2;
        *(__half2*)(o0 + cc) = __floats2half2_rn(oacc[ni][0] * inv0, oacc[ni][1] * inv0);
        *(__half2*)(o1 + cc) = __floats2half2_rn(oacc[ni][2] * inv1, oacc[ni][3] * inv1);
    }
}

// ---------------------------------------------------------------------------
extern "C" void kernel_launch(void* const* d_in, const int* in_sizes, int n_in,
                              void* d_out, int out_size)
{
    const float* x      = (const float*)d_in[0];
    const float* w_qkv  = (const float*)d_in[1];
    const float* w_proj = (const float*)d_in[2];
    const float* b_proj = (const float*)d_in[3];
    float* out = (float*)d_out;

    __half *qkv, *att, *xh, *wqt, *wpt;
    cudaGetSymbolAddress((void**)&qkv, g_qkv);
    cudaGetSymbolAddress((void**)&att, g_att);
    cudaGetSymbolAddress((void**)&xh,  g_xh);
    cudaGetSymbolAddress((void**)&wqt, g_wqt);
    cudaGetSymbolAddress((void**)&wpt, g_wpt);

    const int GSMEM = 3 * GSTG;                 // 98304
    cudaFuncSetAttribute(gemm_h<1>,
                         cudaFuncAttributeMaxDynamicSharedMemorySize, GSMEM);
    cudaFuncSetAttribute(gemm_h<0>,
                         cudaFuncAttributeMaxDynamicSharedMemorySize, GSMEM);
    const int ASMEM = 16384 + 3 * KVSTG;        // 65536
    cudaFuncSetAttribute(attn_h,
                         cudaFuncAttributeMaxDynamicSharedMemorySize, ASMEM);

    // 0) pre-pass: x -> half; weights -> half transposed [N][K]
    f32_to_h<<<512, 256>>>((const float4*)x, (uint2*)xh, M_TOT * DM / 4);
    transpose_h<<<dim3(3 * DM / 32, DM / 32), dim3(32, 8)>>>(w_qkv, wqt, DM, 3 * DM);
    transpose_h<<<dim3(DM / 32, DM / 32), dim3(32, 8)>>>(w_proj, wpt, DM, DM);

    // 1) QKV = xh @ wqt^T  (8192 x 3072 x 1024), fp16 HMMA, half out (Q scaled)
    gemm_h<1><<<dim3(3 * DM / 128, M_TOT / 128), 256, GSMEM>>>(
        xh, wqt, nullptr, qkv, 3 * DM, DM);

    // 2) causal MHA -> att (half)
    attn_h<<<dim3(TSEQ / 128, NB * 16), 256, ASMEM>>>(qkv, att);

    // 3) out = att @ wpt^T + b_proj  (8192 x 1024 x 1024), fp32 out
    gemm_h<0><<<dim3(DM / 128, M_TOT / 128), 256, GSMEM>>>(
        att, wpt, b_proj, out, DM, DM);
}